// round 1
// baseline (speedup 1.0000x reference)
#include <cuda_runtime.h>

// RotaryEmbedding: x (4,16,8192,64) fp32. Rotate first ROTATE=4 pairs
// (elements 0..7) of each 64-float row; copy the rest unchanged.
//
// direction = sigmoid(dparam[0])*2 - 1
// theta_p   = direction * thetas[p]   (p = 0..3)
// xi' =  xi*c + xj*s ;  xj' = -xi*s + xj*c
//
// Strategy: flat float4 traversal. 64 floats/row = 16 float4/row.
// Chunks with (idx & 15) < 2 hold the 4 rotating pairs (2 pairs per float4).
// Purely HBM-bound: 256 MiB traffic, predicted ~38-45 us.

__global__ __launch_bounds__(256) void rope_kernel(
    const float4* __restrict__ x,
    const float*  __restrict__ dparam,
    const float*  __restrict__ thetas,
    float4*       __restrict__ out,
    int n4)
{
    int idx = blockIdx.x * blockDim.x + threadIdx.x;
    if (idx >= n4) return;

    float4 v = x[idx];
    int col4 = idx & 15;            // position within the 64-float row (16 float4s)

    if (col4 < 2) {
        // direction = sigmoid(dparam[0])*2 - 1 = tanh(dparam[0]/2)
        float d = tanhf(0.5f * dparam[0]);
        int p = col4 * 2;           // first pair index in this chunk
        float t0 = d * thetas[p];
        float t1 = d * thetas[p + 1];
        float s0, c0, s1, c1;
        sincosf(t0, &s0, &c0);
        sincosf(t1, &s1, &c1);

        float xi0 = v.x, xj0 = v.y;
        float xi1 = v.z, xj1 = v.w;
        v.x =  xi0 * c0 + xj0 * s0;
        v.y = -xi0 * s0 + xj0 * c0;
        v.z =  xi1 * c1 + xj1 * s1;
        v.w = -xi1 * s1 + xj1 * c1;
    }

    out[idx] = v;
}

extern "C" void kernel_launch(void* const* d_in, const int* in_sizes, int n_in,
                              void* d_out, int out_size)
{
    const float4* x      = (const float4*)d_in[0];
    const float*  dparam = (const float*)d_in[1];
    const float*  thetas = (const float*)d_in[2];
    float4*       out    = (float4*)d_out;

    int n4 = in_sizes[0] / 4;       // 33,554,432 / 4 = 8,388,608 float4 chunks
    int threads = 256;
    int blocks  = (n4 + threads - 1) / threads;
    rope_kernel<<<blocks, threads>>>(x, dparam, thetas, out, n4);
}